// round 14
// baseline (speedup 1.0000x reference)
#include <cuda_runtime.h>
#include <math.h>

#define NP 150000
#define FD 512
#define SD 5000
#define KSEL 512
#define HB 150
#define CHUNK 1000
#define FPS_G 148
#define FPS_ROWS 34
#define ATT_SCALE 0.08838834764831845f
#define FPS_SMEM ((FPS_ROWS*FD+FD+FPS_ROWS)*4)
#define D4(v,j) ((j)==0?(v).x:((j)==1?(v).y:((j)==2?(v).z:(v).w)))

__device__ float g_seg_feat[SD*FD], g_seg_pos[SD*FD], g_q[SD*FD], g_qin[SD*FD];
__device__ float g_Qp[SD*FD], g_o[SD*FD];
__device__ float g_Kp[KSEL*FD], g_KpT[KSEL*FD], g_Vp[KSEL*FD], g_keyfeat[KSEL*FD], g_kin[KSEL*FD];
__device__ float g_att[4*SD*KSEL];
__device__ int g_sorted[NP], g_hist[HB*SD], g_segstart[SD+1], g_minmax[6], g_fps_idx[KSEL];
__device__ unsigned long long g_winner[KSEL], g_rel[KSEL];
__device__ unsigned g_barc;

__device__ __forceinline__ unsigned long long ld_acq_u64(const unsigned long long* p){
    unsigned long long v;
    asm volatile("ld.acquire.gpu.u64 %0, [%1];" : "=l"(v) : "l"(p) : "memory");
    return v;
}
__device__ __forceinline__ void st_rel_u64(unsigned long long* p, unsigned long long v){
    asm volatile("st.release.gpu.u64 [%0], %1;" :: "l"(p), "l"(v) : "memory");
}

// sin(2*pi*u), cos(2*pi*u) entirely in the FMA pipe (no MUFU).
__device__ __forceinline__ void sincos2pi(float u, float& s, float& c){
    float t = 4.0f*u;
    float q = rintf(t);
    float r = (t - q)*1.5707963267948966f;   // [-pi/4, pi/4]
    int qi = (int)q;
    float r2 = r*r, r4 = r2*r2;
    float ps = fmaf(-1.9515296e-4f, r2, 8.3321608e-3f);
    ps = fmaf(ps, r2, -1.6666654e-1f);
    ps = fmaf(ps*r2, r, r);
    float pc = fmaf(2.4433157e-5f, r2, -1.3887316e-3f);
    pc = fmaf(pc, r2, 4.1666645e-2f);
    pc = fmaf(pc, r4, fmaf(-0.5f, r2, 1.0f));
    bool sw = qi & 1;
    float ss = sw ? pc : ps;
    float cc = sw ? ps : pc;
    if (qi & 2) ss = -ss;
    if ((qi+1) & 2) cc = -cc;
    s = ss; c = cc;
}

__global__ void k_init(){
    int t = threadIdx.x;
    if (t < 3) g_minmax[t] = 0x7F7FFFFF;
    else if (t < 6) g_minmax[t] = 0;
    if (t == 0){ g_barc = 0u; g_fps_idx[0] = 0; }
    for (int i = t; i < KSEL; i += 256){ g_winner[i] = 0ULL; g_rel[i] = 0ULL; }
}

__global__ void k_hist(const float* __restrict__ coords, const int* __restrict__ seg){
    __shared__ int sh[SD];
    int t = threadIdx.x, b = blockIdx.x;
    for (int i = t; i < SD; i += 256) sh[i] = 0;
    __syncthreads();
    int start = b*CHUNK;
    float mn0=3.4e38f,mn1=3.4e38f,mn2=3.4e38f,mx0=-3.4e38f,mx1=-3.4e38f,mx2=-3.4e38f;
    for (int p = start + t; p < start + CHUNK; p += 256){
        atomicAdd(&sh[seg[p]], 1);
        float c0=coords[p*3], c1=coords[p*3+1], c2=coords[p*3+2];
        mn0=fminf(mn0,c0); mn1=fminf(mn1,c1); mn2=fminf(mn2,c2);
        mx0=fmaxf(mx0,c0); mx1=fmaxf(mx1,c1); mx2=fmaxf(mx2,c2);
    }
    __syncthreads();
    for (int s = t; s < SD; s += 256) g_hist[b*SD + s] = sh[s];
    #pragma unroll
    for (int o = 16; o; o >>= 1){
        mn0=fminf(mn0,__shfl_xor_sync(~0u,mn0,o)); mn1=fminf(mn1,__shfl_xor_sync(~0u,mn1,o));
        mn2=fminf(mn2,__shfl_xor_sync(~0u,mn2,o)); mx0=fmaxf(mx0,__shfl_xor_sync(~0u,mx0,o));
        mx1=fmaxf(mx1,__shfl_xor_sync(~0u,mx1,o)); mx2=fmaxf(mx2,__shfl_xor_sync(~0u,mx2,o));
    }
    if ((t & 31) == 0){
        atomicMin(&g_minmax[0], __float_as_int(mn0)); atomicMin(&g_minmax[1], __float_as_int(mn1));
        atomicMin(&g_minmax[2], __float_as_int(mn2)); atomicMax(&g_minmax[3], __float_as_int(mx0));
        atomicMax(&g_minmax[4], __float_as_int(mx1)); atomicMax(&g_minmax[5], __float_as_int(mx2));
    }
}

__global__ void k_scan(){
    __shared__ int stot[SD];
    __shared__ int gsum[1024];
    int t = threadIdx.x;
    for (int s = t; s < SD; s += 1024){
        int run = 0;
        for (int b = 0; b < HB; b++){ int v = g_hist[b*SD+s]; g_hist[b*SD+s] = run; run += v; }
        stot[s] = run;
    }
    __syncthreads();
    int base = t*5, loc[5], sum = 0;
    #pragma unroll
    for (int i = 0; i < 5; i++){ loc[i] = sum; if (base+i < SD) sum += stot[base+i]; }
    gsum[t] = sum;
    __syncthreads();
    for (int off = 1; off < 1024; off <<= 1){
        int add = (t >= off) ? gsum[t-off] : 0;
        __syncthreads(); gsum[t] += add; __syncthreads();
    }
    int excl = (t > 0) ? gsum[t-1] : 0;
    #pragma unroll
    for (int i = 0; i < 5; i++) if (base+i < SD) g_segstart[base+i] = excl + loc[i];
    if (t == 1023) g_segstart[SD] = gsum[1023];
    __syncthreads();
    for (int s = t; s < SD; s += 1024){
        int o = g_segstart[s];
        for (int b = 0; b < HB; b++) g_hist[b*SD+s] += o;
    }
}

__global__ void k_place(const int* __restrict__ seg){
    __shared__ int cur[SD];
    __shared__ int psg[CHUNK];
    int t = threadIdx.x, b = blockIdx.x;
    for (int s = t; s < SD; s += 256) cur[s] = g_hist[b*SD + s];
    for (int i = t; i < CHUNK; i += 256) psg[i] = seg[b*CHUNK + i];
    __syncthreads();
    if (t < 32){
        for (int bs = 0; bs < CHUNK; bs += 32){
            int i = bs + t;
            bool v = i < CHUNK;
            int s = v ? psg[i] : -1 - t;
            unsigned peers = __match_any_sync(0xFFFFFFFFu, s);
            int leader = __ffs(peers) - 1;
            int rank = __popc(peers & ((1u << t) - 1u));
            int pos = 0;
            if (t == leader && v){ pos = cur[s]; cur[s] = pos + __popc(peers); }
            pos = __shfl_sync(0xFFFFFFFFu, pos, leader);
            if (v) g_sorted[pos + rank] = b*CHUNK + i;
        }
    }
}

__global__ void k_segreduce(const float* __restrict__ pf, const float* __restrict__ coords,
                            const float* __restrict__ fB){
    __shared__ float sB0[256], sB1[256], sB2[256];
    int t = threadIdx.x, s = blockIdx.x;
    sB0[t] = fB[t]; sB1[t] = fB[256+t]; sB2[t] = fB[512+t];
    float mn0 = __int_as_float(g_minmax[0]), mn1 = __int_as_float(g_minmax[1]), mn2 = __int_as_float(g_minmax[2]);
    float i0 = 1.f/(__int_as_float(g_minmax[3])-mn0+1e-6f);
    float i1 = 1.f/(__int_as_float(g_minmax[4])-mn1+1e-6f);
    float i2 = 1.f/(__int_as_float(g_minmax[5])-mn2+1e-6f);
    __syncthreads();
    int st = g_segstart[s], en = g_segstart[s+1];
    float aS=0.f, aC=0.f, a0=0.f, a1=0.f;
    for (int i = st; i < en; i++){
        int p = g_sorted[i];
        float c0=(coords[p*3]-mn0)*i0, c1=(coords[p*3+1]-mn1)*i1, c2=(coords[p*3+2]-mn2)*i2;
        float u = c0*sB0[t] + c1*sB1[t] + c2*sB2[t];   // angle = 2*pi*u
        float sv, cv; sincos2pi(u, sv, cv);
        aS += sv; aC += cv;
        const float* r = pf + (size_t)p*FD;
        a0 += r[t]; a1 += r[t+256];
    }
    float ic = 1.f/fmaxf((float)(en-st), 1.f);
    int o0 = s*FD + t, o1 = o0 + 256;
    g_seg_pos[o0] = aS*ic; g_seg_pos[o1] = aC*ic;
    float f0 = a0*ic, f1 = a1*ic;
    g_seg_feat[o0]=f0; g_seg_feat[o1]=f1; g_q[o0]=f0; g_q[o1]=f1;
}

// FPS: 148 CTAs x 1024 threads x 34 rows (~1 row/warp). SMEM-staged scur,
// register-hoisted per lane (bitwise-identical distances to R11).
// Consensus: atomicMax winner + arrival counter; the LAST arriver fences,
// reads the winner, and release-stores it into g_rel[step]; all others spin
// with acquire loads on that single word (same-address L2 broadcast).
__global__ void __launch_bounds__(1024) k_fps(){
    extern __shared__ float sm[];
    float* srows = sm;                    // FPS_ROWS*FD
    float* scur  = sm + FPS_ROWS*FD;      // FD
    float* sdmin = scur + FD;             // FPS_ROWS
    __shared__ int s_cur;
    int t = threadIdx.x, b = blockIdx.x;
    int r0 = b*FPS_ROWS;
    int nrows = SD - r0; if (nrows > FPS_ROWS) nrows = FPS_ROWS; if (nrows < 0) nrows = 0;
    for (int i = t; i < nrows*FD; i += 1024) srows[i] = g_seg_pos[r0*FD + i];
    for (int r = t; r < nrows; r += 1024) sdmin[r] = 1e10f;
    if (t == 0) s_cur = 0;
    __syncthreads();
    int w = t>>5, lane = t&31;
    for (int step = 1; step < KSEL; step++){
        int cur = s_cur;
        for (int e = t; e < FD; e += 1024) scur[e] = g_seg_pos[cur*FD + e];
        __syncthreads();
        float c[16];
        #pragma unroll
        for (int i = 0; i < 16; i++) c[i] = scur[lane + 32*i];
        for (int r = w; r < nrows; r += 32){
            const float* rp = srows + r*FD + lane;
            float acc = 0.f;
            #pragma unroll
            for (int i = 0; i < 16; i++){ float d = rp[32*i] - c[i]; acc = fmaf(d,d,acc); }
            #pragma unroll
            for (int o = 16; o; o >>= 1) acc += __shfl_xor_sync(~0u, acc, o);
            if (lane == 0) sdmin[r] = fminf(sdmin[r], acc);
        }
        __syncthreads();
        if (w == 0){
            unsigned long long best = 0ULL;
            for (int r = lane; r < nrows; r += 32){
                unsigned long long pk = ((unsigned long long)__float_as_uint(sdmin[r])<<32)
                                      | (unsigned long long)(0xFFFFFFFFu - (unsigned)(r0+r));
                if (pk > best) best = pk;
            }
            #pragma unroll
            for (int o = 16; o; o >>= 1){
                unsigned long long v = __shfl_xor_sync(~0u, best, o);
                if (v > best) best = v;
            }
            if (lane == 0){
                atomicMax(&g_winner[step], best);
                __threadfence();                       // release our winner update
                unsigned old = atomicAdd(&g_barc, 1u); // publish arrival
                unsigned long long wv;
                if (old == (unsigned)step*FPS_G - 1u){
                    __threadfence();                   // sync with all prior fences
                    wv = ld_acq_u64(&g_winner[step]);  // final max
                    st_rel_u64(&g_rel[step], wv);      // broadcast result
                } else {
                    while ((wv = ld_acq_u64(&g_rel[step])) == 0ULL) { }
                }
                int sel = (int)(0xFFFFFFFFu - (unsigned)(wv & 0xFFFFFFFFull));
                s_cur = sel;
                if (b == 0) g_fps_idx[step] = sel;
            }
        }
        __syncthreads();
    }
}

__global__ void k_gather(){
    int k = blockIdx.x, t = threadIdx.x;
    int s = g_fps_idx[k];
    float f0 = g_seg_feat[s*FD+t], f1 = g_seg_feat[s*FD+t+256];
    float p0 = g_seg_pos[s*FD+t],  p1 = g_seg_pos[s*FD+t+256];
    g_keyfeat[k*FD+t] = f0;     g_keyfeat[k*FD+t+256] = f1;
    g_kin[k*FD+t] = f0+p0;      g_kin[k*FD+t+256] = f1+p1;
}

__global__ void k_ln(const float* __restrict__ g, const float* __restrict__ b){
    __shared__ float rs[8], rq[8], mr[2];
    int s = blockIdx.x, t = threadIdx.x;
    const float* xr = g_q + (size_t)s*FD;
    float x0 = xr[t], x1 = xr[t+256];
    float su = x0+x1, sq = x0*x0 + x1*x1;
    #pragma unroll
    for (int o = 16; o; o >>= 1){ su += __shfl_xor_sync(~0u,su,o); sq += __shfl_xor_sync(~0u,sq,o); }
    if ((t&31)==0){ rs[t>>5]=su; rq[t>>5]=sq; }
    __syncthreads();
    if (t == 0){
        float S=0.f,Q=0.f;
        #pragma unroll
        for (int i=0;i<8;i++){ S+=rs[i]; Q+=rq[i]; }
        float m = S*(1.f/512.f);
        mr[0]=m; mr[1]=rsqrtf(Q*(1.f/512.f)-m*m+1e-5f);
    }
    __syncthreads();
    float m = mr[0], r = mr[1];
    size_t o0 = (size_t)s*FD+t, o1 = o0+256;
    g_qin[o0] = (x0-m)*r*g[t]+b[t] + g_seg_pos[o0];
    g_qin[o1] = (x1-m)*r*g[t+256]+b[t+256] + g_seg_pos[o1];
}

// small GEMM (64x64 tile) for M=512 projections
__global__ void __launch_bounds__(256) k_gemm(const float* __restrict__ A, int lda,
    const float* __restrict__ B, const float* __restrict__ bias,
    float* __restrict__ C, int ldc, int M, int Kd)
{
    __shared__ float As[16][68], Bs[16][68];
    int t = threadIdx.x;
    int bm = blockIdx.x*64, bn = blockIdx.y*64;
    int ar = t>>2, ac = (t&3)*4, ty = t>>4, tx = t&15;
    float acc[4][4] = {};
    for (int kk = 0; kk < Kd; kk += 16){
        float4 av = make_float4(0.f,0.f,0.f,0.f);
        if (bm+ar < M) av = *(const float4*)(A + (size_t)(bm+ar)*lda + kk + ac);
        float bv[4];
        #pragma unroll
        for (int j = 0; j < 4; j++){
            int i = t + j*256;
            bv[j] = B[(size_t)(kk+(i>>6))*FD + bn + (i&63)];
        }
        __syncthreads();
        As[ac][ar]=av.x; As[ac+1][ar]=av.y; As[ac+2][ar]=av.z; As[ac+3][ar]=av.w;
        #pragma unroll
        for (int j = 0; j < 4; j++){ int i = t + j*256; Bs[i>>6][i&63] = bv[j]; }
        __syncthreads();
        #pragma unroll
        for (int k = 0; k < 16; k++){
            float4 a4 = *(float4*)&As[k][ty*4];
            float4 b4 = *(float4*)&Bs[k][tx*4];
            #pragma unroll
            for (int i = 0; i < 4; i++)
                #pragma unroll
                for (int j = 0; j < 4; j++)
                    acc[i][j] = fmaf(D4(a4,i), D4(b4,j), acc[i][j]);
        }
    }
    #pragma unroll
    for (int i = 0; i < 4; i++){
        int r = bm + ty*4 + i;
        if (r < M){
            float4 bi = *(const float4*)(bias + bn + tx*4);
            float4 o = make_float4(acc[i][0]+bi.x,acc[i][1]+bi.y,acc[i][2]+bi.z,acc[i][3]+bi.w);
            *(float4*)(C + (size_t)r*ldc + bn + tx*4) = o;
        }
    }
}

// big GEMM: 128x128 tile, 8x8 microtile, double-buffered; blockIdx.z strides
__global__ void __launch_bounds__(256) k_gemm128(const float* __restrict__ A, int lda, size_t sA,
    const float* __restrict__ B, int ldb, size_t sB, const float* __restrict__ bias,
    float* __restrict__ C, int ldc, size_t sC, const float* __restrict__ R, int M, int Kd)
{
    A += (size_t)blockIdx.z*sA; B += (size_t)blockIdx.z*sB; C += (size_t)blockIdx.z*sC;
    __shared__ float As[2][8][128];
    __shared__ float Bs[2][8][128];
    int t = threadIdx.x;
    int bm = blockIdx.x*128, bn = blockIdx.y*128;
    int ty = t>>4, tx = t&15;
    int arow = t>>1, acol = (t&1)*4;
    int brow = t>>5, bcol = (t&31)*4;
    bool aval = (bm + arow) < M;
    const float* Ap = A + (size_t)(bm+arow)*lda + acol;
    const float* Bp = B + (size_t)brow*ldb + bn + bcol;
    float acc[8][8] = {};
    float4 pa = aval ? *(const float4*)Ap : make_float4(0.f,0.f,0.f,0.f);
    float4 pb = *(const float4*)Bp;
    As[0][acol+0][arow]=pa.x; As[0][acol+1][arow]=pa.y; As[0][acol+2][arow]=pa.z; As[0][acol+3][arow]=pa.w;
    *(float4*)&Bs[0][brow][bcol] = pb;
    __syncthreads();
    int buf = 0;
    for (int kk = 8; kk <= Kd; kk += 8){
        bool more = kk < Kd;
        if (more){
            pa = aval ? *(const float4*)(Ap + kk) : make_float4(0.f,0.f,0.f,0.f);
            pb = *(const float4*)(Bp + (size_t)kk*ldb);
        }
        #pragma unroll
        for (int k = 0; k < 8; k++){
            float4 a0 = *(float4*)&As[buf][k][ty*8];
            float4 a1 = *(float4*)&As[buf][k][ty*8+4];
            float4 b0 = *(float4*)&Bs[buf][k][tx*8];
            float4 b1 = *(float4*)&Bs[buf][k][tx*8+4];
            float av[8] = {a0.x,a0.y,a0.z,a0.w,a1.x,a1.y,a1.z,a1.w};
            float bv[8] = {b0.x,b0.y,b0.z,b0.w,b1.x,b1.y,b1.z,b1.w};
            #pragma unroll
            for (int i = 0; i < 8; i++)
                #pragma unroll
                for (int j = 0; j < 8; j++)
                    acc[i][j] = fmaf(av[i], bv[j], acc[i][j]);
        }
        if (more){
            As[buf^1][acol+0][arow]=pa.x; As[buf^1][acol+1][arow]=pa.y;
            As[buf^1][acol+2][arow]=pa.z; As[buf^1][acol+3][arow]=pa.w;
            *(float4*)&Bs[buf^1][brow][bcol] = pb;
        }
        __syncthreads();
        buf ^= 1;
    }
    #pragma unroll
    for (int i = 0; i < 8; i++){
        int r = bm + ty*8 + i;
        if (r < M){
            #pragma unroll
            for (int jj = 0; jj < 2; jj++){
                int c = bn + tx*8 + jj*4;
                float4 o = make_float4(acc[i][jj*4],acc[i][jj*4+1],acc[i][jj*4+2],acc[i][jj*4+3]);
                if (bias){
                    float4 bi = *(const float4*)(bias + c);
                    o.x+=bi.x; o.y+=bi.y; o.z+=bi.z; o.w+=bi.w;
                }
                if (R){
                    float4 r4 = *(const float4*)(R + (size_t)r*ldc + c);
                    o.x+=r4.x; o.y+=r4.y; o.z+=r4.z; o.w+=r4.w;
                }
                *(float4*)(C + (size_t)r*ldc + c) = o;
            }
        }
    }
}

__global__ void k_transK(){
    int i = blockIdx.x*256 + threadIdx.x;   // 512*512
    int n = i & 511, r = i >> 9;            // r = h*128+k
    g_KpT[(r>>7)*65536 + (r&127)*512 + n] = g_Kp[n*512 + r];
}

__global__ void k_softmax(){
    int w = threadIdx.x>>5, lane = threadIdx.x&31;
    size_t row = (size_t)blockIdx.x*8 + w;
    float* p = g_att + row*512;
    float v[16], mx = -3.4e38f;
    #pragma unroll
    for (int i=0;i<16;i++){ v[i] = p[lane+32*i]*ATT_SCALE; mx = fmaxf(mx, v[i]); }
    #pragma unroll
    for (int o=16;o;o>>=1) mx = fmaxf(mx, __shfl_xor_sync(~0u,mx,o));
    float s = 0.f;
    #pragma unroll
    for (int i=0;i<16;i++){ v[i] = __expf(v[i]-mx); s += v[i]; }
    #pragma unroll
    for (int o=16;o;o>>=1) s += __shfl_xor_sync(~0u,s,o);
    float inv = 1.f/s;
    #pragma unroll
    for (int i=0;i<16;i++) p[lane+32*i] = v[i]*inv;
}

__global__ void __launch_bounds__(256) k_final(const float* __restrict__ pf, const int* __restrict__ seg,
    const float* __restrict__ c1g, const float* __restrict__ c1b, const float* __restrict__ c1w,
    const float* __restrict__ c1bias, const float* __restrict__ cw, const float* __restrict__ cb,
    float* __restrict__ out)
{
    __shared__ float swT[20][512];
    __shared__ float sg[512], sb[512], sw1[512], scb[20], sc1b;
    int t = threadIdx.x;
    for (int i = t; i < 512*20; i += 256) swT[i%20][i/20] = cw[i];
    for (int i = t; i < 512; i += 256){ sg[i]=c1g[i]; sb[i]=c1b[i]; sw1[i]=c1w[i]; }
    if (t < 20) scb[t] = cb[t];
    if (t == 32) sc1b = c1bias[0];
    __syncthreads();
    int w = t>>5, lane = t&31;
    for (int p = blockIdx.x*8 + w; p < NP; p += gridDim.x*8){
        int s = seg[p];
        const float* fr = g_q + (size_t)s*512;
        const float* pr = pf + (size_t)p*512;
        float f[16], x[16], a[16], su = 0.f, sq = 0.f;
        #pragma unroll
        for (int i=0;i<16;i++){
            int e = lane + 32*i;
            f[i] = fr[e]; x[i] = pr[e];
            a[i] = fabsf(f[i]-x[i]);
            su += a[i]; sq += a[i]*a[i];
        }
        #pragma unroll
        for (int o=16;o;o>>=1){ su += __shfl_xor_sync(~0u,su,o); sq += __shfl_xor_sync(~0u,sq,o); }
        float m = su*(1.f/512.f);
        float rst = rsqrtf(sq*(1.f/512.f) - m*m + 1e-5f);
        float dt = 0.f;
        #pragma unroll
        for (int i=0;i<16;i++){ int e = lane+32*i; dt += ((a[i]-m)*rst*sg[e]+sb[e])*sw1[e]; }
        #pragma unroll
        for (int o=16;o;o>>=1) dt += __shfl_xor_sync(~0u,dt,o);
        float wg = 1.f/(1.f+__expf(-(dt+sc1b)));
        float bl[16];
        #pragma unroll
        for (int i=0;i<16;i++) bl[i] = x[i] + wg*(f[i]-x[i]);
        float* op = out + (size_t)p*20;
        for (int o = 0; o < 20; o++){
            float acc = 0.f;
            #pragma unroll
            for (int i=0;i<16;i++) acc += bl[i]*swT[o][lane+32*i];
            #pragma unroll
            for (int off=16;off;off>>=1) acc += __shfl_xor_sync(~0u,acc,off);
            if (lane == 0) op[o] = acc + scb[o];
        }
    }
}

extern "C" void kernel_launch(void* const* d_in, const int* in_sizes, int n_in,
                              void* d_out, int out_size) {
    const float* pf  = (const float*)d_in[0];
    const float* co  = (const float*)d_in[1];
    const float* fB  = (const float*)d_in[2];
    const float* lng = (const float*)d_in[3];
    const float* lnb = (const float*)d_in[4];
    const float* Wq  = (const float*)d_in[5];
    const float* Wk  = (const float*)d_in[6];
    const float* Wv  = (const float*)d_in[7];
    const float* Wo  = (const float*)d_in[8];
    const float* bq  = (const float*)d_in[9];
    const float* bk  = (const float*)d_in[10];
    const float* bv  = (const float*)d_in[11];
    const float* bo  = (const float*)d_in[12];
    const float* c1g = (const float*)d_in[13];
    const float* c1b = (const float*)d_in[14];
    const float* c1w = (const float*)d_in[15];
    const float* c1bias = (const float*)d_in[16];
    const float* cw  = (const float*)d_in[17];
    const float* cb  = (const float*)d_in[18];
    const int*   seg = (const int*)d_in[19];
    float* out = (float*)d_out;

    static int cfg = 0;
    if (!cfg){ cudaFuncSetAttribute(k_fps, cudaFuncAttributeMaxDynamicSharedMemorySize, FPS_SMEM); cfg = 1; }

    float *gqin, *gQp, *gKp, *gKpT, *gVp, *gkf, *gkin, *gatt, *go, *gq;
    cudaGetSymbolAddress((void**)&gqin, g_qin);
    cudaGetSymbolAddress((void**)&gQp,  g_Qp);
    cudaGetSymbolAddress((void**)&gKp,  g_Kp);
    cudaGetSymbolAddress((void**)&gKpT, g_KpT);
    cudaGetSymbolAddress((void**)&gVp,  g_Vp);
    cudaGetSymbolAddress((void**)&gkf,  g_keyfeat);
    cudaGetSymbolAddress((void**)&gkin, g_kin);
    cudaGetSymbolAddress((void**)&gatt, g_att);
    cudaGetSymbolAddress((void**)&go,   g_o);
    cudaGetSymbolAddress((void**)&gq,   g_q);

    k_init<<<1,256>>>();
    k_hist<<<HB,256>>>(co, seg);
    k_scan<<<1,1024>>>();
    k_place<<<HB,256>>>(seg);
    k_segreduce<<<SD,256>>>(pf, co, fB);
    k_fps<<<FPS_G,1024,FPS_SMEM>>>();
    k_gather<<<KSEL,256>>>();

    dim3 gBig(40,4,1), gLog(40,4,4), gAV(40,1,4), gK(8,8);
    size_t sAtt = (size_t)SD*512;
    for (int L = 0; L < 2; L++){
        const float* wq = Wq + (size_t)L*FD*FD; const float* wk = Wk + (size_t)L*FD*FD;
        const float* wv = Wv + (size_t)L*FD*FD; const float* wo = Wo + (size_t)L*FD*FD;
        k_ln<<<SD,256>>>(lng + L*FD, lnb + L*FD);
        k_gemm128<<<gBig,256>>>(gqin,512,0, wq,512,0, bq+L*FD, gQp,512,0, 0, SD, 512);
        k_gemm<<<gK,256>>>(gkin,512, wk, bk+L*FD, gKp,512, KSEL, 512);
        k_gemm<<<gK,256>>>(gkf, 512, wv, bv+L*FD, gVp,512, KSEL, 512);
        k_transK<<<1024,256>>>();
        k_gemm128<<<gLog,256>>>(gQp,512,128, gKpT,512,65536, 0, gatt,512,sAtt, 0, SD, 128);
        k_softmax<<<SD*4/8,256>>>();
        k_gemm128<<<gAV,256>>>(gatt,512,sAtt, gVp,512,128, 0, go,512,128, 0, SD, 512);
        k_gemm128<<<gBig,256>>>(go,512,0, wo,512,0, bo+L*FD, gq,512,0, gq, SD, 512);
    }
    k_final<<<600,256>>>(pf, seg, c1g, c1b, c1w, c1bias, cw, cb, out);
}

// round 15
// speedup vs baseline: 1.1986x; 1.1986x over previous
#include <cuda_runtime.h>
#include <math.h>

#define NP 150000
#define FD 512
#define SD 5000
#define KSEL 512
#define HB 150
#define CHUNK 1000
#define FPS_G 148
#define FPS_ROWS 34
#define ATT_SCALE 0.08838834764831845f
#define FPS_SMEM ((FPS_ROWS*FD+FD+FPS_ROWS)*4 + 16*8)
#define D4(v,j) ((j)==0?(v).x:((j)==1?(v).y:((j)==2?(v).z:(v).w)))

__device__ float g_seg_feat[SD*FD], g_seg_pos[SD*FD], g_q[SD*FD], g_qin[SD*FD];
__device__ float g_Qp[SD*FD], g_o[SD*FD];
__device__ float g_KpT[KSEL*FD], g_Vp[KSEL*FD], g_keyfeat[KSEL*FD], g_kin[KSEL*FD];
__device__ float g_att[4*SD*KSEL];
__device__ int g_sorted[NP], g_hist[HB*SD], g_segstart[SD+1], g_minmax[6], g_fps_idx[KSEL];
__device__ unsigned long long g_winner[KSEL];
__device__ unsigned g_barc;

__device__ __forceinline__ unsigned ld_acq_u32(const unsigned* p){
    unsigned v;
    asm volatile("ld.acquire.gpu.u32 %0, [%1];" : "=r"(v) : "l"(p) : "memory");
    return v;
}
__device__ __forceinline__ unsigned long long ld_acq_u64(const unsigned long long* p){
    unsigned long long v;
    asm volatile("ld.acquire.gpu.u64 %0, [%1];" : "=l"(v) : "l"(p) : "memory");
    return v;
}

// sin(2*pi*u), cos(2*pi*u) entirely in the FMA pipe (no MUFU).
__device__ __forceinline__ void sincos2pi(float u, float& s, float& c){
    float t = 4.0f*u;
    float q = rintf(t);
    float r = (t - q)*1.5707963267948966f;   // [-pi/4, pi/4]
    int qi = (int)q;
    float r2 = r*r, r4 = r2*r2;
    float ps = fmaf(-1.9515296e-4f, r2, 8.3321608e-3f);
    ps = fmaf(ps, r2, -1.6666654e-1f);
    ps = fmaf(ps*r2, r, r);
    float pc = fmaf(2.4433157e-5f, r2, -1.3887316e-3f);
    pc = fmaf(pc, r2, 4.1666645e-2f);
    pc = fmaf(pc, r4, fmaf(-0.5f, r2, 1.0f));
    bool sw = qi & 1;
    float ss = sw ? pc : ps;
    float cc = sw ? ps : pc;
    if (qi & 2) ss = -ss;
    if ((qi+1) & 2) cc = -cc;
    s = ss; c = cc;
}

__global__ void k_init(){
    int t = threadIdx.x;
    if (t < 3) g_minmax[t] = 0x7F7FFFFF;
    else if (t < 6) g_minmax[t] = 0;
    if (t == 0){ g_barc = 0u; g_fps_idx[0] = 0; }
    for (int i = t; i < KSEL; i += 256) g_winner[i] = 0ULL;
}

__global__ void k_hist(const float* __restrict__ coords, const int* __restrict__ seg){
    __shared__ int sh[SD];
    int t = threadIdx.x, b = blockIdx.x;
    for (int i = t; i < SD; i += 256) sh[i] = 0;
    __syncthreads();
    int start = b*CHUNK;
    float mn0=3.4e38f,mn1=3.4e38f,mn2=3.4e38f,mx0=-3.4e38f,mx1=-3.4e38f,mx2=-3.4e38f;
    for (int p = start + t; p < start + CHUNK; p += 256){
        atomicAdd(&sh[seg[p]], 1);
        float c0=coords[p*3], c1=coords[p*3+1], c2=coords[p*3+2];
        mn0=fminf(mn0,c0); mn1=fminf(mn1,c1); mn2=fminf(mn2,c2);
        mx0=fmaxf(mx0,c0); mx1=fmaxf(mx1,c1); mx2=fmaxf(mx2,c2);
    }
    __syncthreads();
    for (int s = t; s < SD; s += 256) g_hist[b*SD + s] = sh[s];
    #pragma unroll
    for (int o = 16; o; o >>= 1){
        mn0=fminf(mn0,__shfl_xor_sync(~0u,mn0,o)); mn1=fminf(mn1,__shfl_xor_sync(~0u,mn1,o));
        mn2=fminf(mn2,__shfl_xor_sync(~0u,mn2,o)); mx0=fmaxf(mx0,__shfl_xor_sync(~0u,mx0,o));
        mx1=fmaxf(mx1,__shfl_xor_sync(~0u,mx1,o)); mx2=fmaxf(mx2,__shfl_xor_sync(~0u,mx2,o));
    }
    if ((t & 31) == 0){
        atomicMin(&g_minmax[0], __float_as_int(mn0)); atomicMin(&g_minmax[1], __float_as_int(mn1));
        atomicMin(&g_minmax[2], __float_as_int(mn2)); atomicMax(&g_minmax[3], __float_as_int(mx0));
        atomicMax(&g_minmax[4], __float_as_int(mx1)); atomicMax(&g_minmax[5], __float_as_int(mx2));
    }
}

__global__ void k_scan(){
    __shared__ int stot[SD];
    __shared__ int gsum[1024];
    int t = threadIdx.x;
    for (int s = t; s < SD; s += 1024){
        int run = 0;
        for (int b = 0; b < HB; b++){ int v = g_hist[b*SD+s]; g_hist[b*SD+s] = run; run += v; }
        stot[s] = run;
    }
    __syncthreads();
    int base = t*5, loc[5], sum = 0;
    #pragma unroll
    for (int i = 0; i < 5; i++){ loc[i] = sum; if (base+i < SD) sum += stot[base+i]; }
    gsum[t] = sum;
    __syncthreads();
    for (int off = 1; off < 1024; off <<= 1){
        int add = (t >= off) ? gsum[t-off] : 0;
        __syncthreads(); gsum[t] += add; __syncthreads();
    }
    int excl = (t > 0) ? gsum[t-1] : 0;
    #pragma unroll
    for (int i = 0; i < 5; i++) if (base+i < SD) g_segstart[base+i] = excl + loc[i];
    if (t == 1023) g_segstart[SD] = gsum[1023];
    __syncthreads();
    for (int s = t; s < SD; s += 1024){
        int o = g_segstart[s];
        for (int b = 0; b < HB; b++) g_hist[b*SD+s] += o;
    }
}

__global__ void k_place(const int* __restrict__ seg){
    __shared__ int cur[SD];
    __shared__ int psg[CHUNK];
    int t = threadIdx.x, b = blockIdx.x;
    for (int s = t; s < SD; s += 256) cur[s] = g_hist[b*SD + s];
    for (int i = t; i < CHUNK; i += 256) psg[i] = seg[b*CHUNK + i];
    __syncthreads();
    if (t < 32){
        for (int bs = 0; bs < CHUNK; bs += 32){
            int i = bs + t;
            bool v = i < CHUNK;
            int s = v ? psg[i] : -1 - t;
            unsigned peers = __match_any_sync(0xFFFFFFFFu, s);
            int leader = __ffs(peers) - 1;
            int rank = __popc(peers & ((1u << t) - 1u));
            int pos = 0;
            if (t == leader && v){ pos = cur[s]; cur[s] = pos + __popc(peers); }
            pos = __shfl_sync(0xFFFFFFFFu, pos, leader);
            if (v) g_sorted[pos + rank] = b*CHUNK + i;
        }
    }
}

__global__ void k_segreduce(const float* __restrict__ pf, const float* __restrict__ coords,
                            const float* __restrict__ fB){
    __shared__ float sB0[256], sB1[256], sB2[256];
    int t = threadIdx.x, s = blockIdx.x;
    sB0[t] = fB[t]; sB1[t] = fB[256+t]; sB2[t] = fB[512+t];
    float mn0 = __int_as_float(g_minmax[0]), mn1 = __int_as_float(g_minmax[1]), mn2 = __int_as_float(g_minmax[2]);
    float i0 = 1.f/(__int_as_float(g_minmax[3])-mn0+1e-6f);
    float i1 = 1.f/(__int_as_float(g_minmax[4])-mn1+1e-6f);
    float i2 = 1.f/(__int_as_float(g_minmax[5])-mn2+1e-6f);
    __syncthreads();
    int st = g_segstart[s], en = g_segstart[s+1];
    float aS=0.f, aC=0.f, a0=0.f, a1=0.f;
    for (int i = st; i < en; i++){
        int p = g_sorted[i];
        float c0=(coords[p*3]-mn0)*i0, c1=(coords[p*3+1]-mn1)*i1, c2=(coords[p*3+2]-mn2)*i2;
        float u = c0*sB0[t] + c1*sB1[t] + c2*sB2[t];   // angle = 2*pi*u
        float sv, cv; sincos2pi(u, sv, cv);
        aS += sv; aC += cv;
        const float* r = pf + (size_t)p*FD;
        a0 += r[t]; a1 += r[t+256];
    }
    float ic = 1.f/fmaxf((float)(en-st), 1.f);
    int o0 = s*FD + t, o1 = o0 + 256;
    g_seg_pos[o0] = aS*ic; g_seg_pos[o1] = aC*ic;
    float f0 = a0*ic, f1 = a1*ic;
    g_seg_feat[o0]=f0; g_seg_feat[o1]=f1; g_q[o0]=f0; g_q[o1]=f1;
}

// FPS: R11 protocol verbatim (atomicMax + counter + acquire spin), 148x512x34.
// Only change: per-warp running argmax fused into the distance loop
// (exact min/pack/max ops -> bitwise-identical selections).
__global__ void __launch_bounds__(512) k_fps(){
    extern __shared__ float sm[];
    float* srows = sm;                    // FPS_ROWS*FD
    float* scur  = sm + FPS_ROWS*FD;      // FD
    float* sdmin = scur + FD;             // FPS_ROWS
    unsigned long long* sbest = (unsigned long long*)(sdmin + FPS_ROWS);  // 16
    __shared__ int s_cur;
    int t = threadIdx.x, b = blockIdx.x;
    int r0 = b*FPS_ROWS;
    int nrows = SD - r0; if (nrows > FPS_ROWS) nrows = FPS_ROWS; if (nrows < 0) nrows = 0;
    for (int i = t; i < nrows*FD; i += 512) srows[i] = g_seg_pos[r0*FD + i];
    for (int r = t; r < nrows; r += 512) sdmin[r] = 1e10f;
    if (t == 0) s_cur = 0;
    __syncthreads();
    int w = t>>5, lane = t&31;
    for (int step = 1; step < KSEL; step++){
        int cur = s_cur;
        for (int e = t; e < FD; e += 512) scur[e] = g_seg_pos[cur*FD + e];
        __syncthreads();
        float c[16];
        #pragma unroll
        for (int i = 0; i < 16; i++) c[i] = scur[lane + 32*i];
        unsigned long long wbest = 0ULL;
        for (int r = w; r < nrows; r += 16){
            const float* rp = srows + r*FD + lane;
            float acc = 0.f;
            #pragma unroll
            for (int i = 0; i < 16; i++){ float d = rp[32*i] - c[i]; acc = fmaf(d,d,acc); }
            #pragma unroll
            for (int o = 16; o; o >>= 1) acc += __shfl_xor_sync(~0u, acc, o);
            if (lane == 0){
                float nv = fminf(sdmin[r], acc);
                sdmin[r] = nv;
                unsigned long long pk = ((unsigned long long)__float_as_uint(nv)<<32)
                                      | (unsigned long long)(0xFFFFFFFFu - (unsigned)(r0+r));
                if (pk > wbest) wbest = pk;
            }
        }
        if (lane == 0) sbest[w] = wbest;
        __syncthreads();
        if (w == 0){
            unsigned long long best = (lane < 16) ? sbest[lane] : 0ULL;
            #pragma unroll
            for (int o = 16; o; o >>= 1){
                unsigned long long v = __shfl_xor_sync(~0u, best, o);
                if (v > best) best = v;
            }
            if (lane == 0){
                atomicMax(&g_winner[step], best);
                __threadfence();                       // release our winner update
                atomicAdd(&g_barc, 1u);                // publish arrival
                unsigned target = (unsigned)step * FPS_G;
                while (ld_acq_u32(&g_barc) < target) { }   // acquire: sync with last arriver
                unsigned long long wv = ld_acq_u64(&g_winner[step]);
                int sel = (int)(0xFFFFFFFFu - (unsigned)(wv & 0xFFFFFFFFull));
                s_cur = sel;
                if (b == 0) g_fps_idx[step] = sel;
            }
        }
        __syncthreads();
    }
}

__global__ void k_gather(){
    int k = blockIdx.x, t = threadIdx.x;
    int s = g_fps_idx[k];
    float f0 = g_seg_feat[s*FD+t], f1 = g_seg_feat[s*FD+t+256];
    float p0 = g_seg_pos[s*FD+t],  p1 = g_seg_pos[s*FD+t+256];
    g_keyfeat[k*FD+t] = f0;     g_keyfeat[k*FD+t+256] = f1;
    g_kin[k*FD+t] = f0+p0;      g_kin[k*FD+t+256] = f1+p1;
}

__global__ void k_ln(const float* __restrict__ g, const float* __restrict__ b){
    __shared__ float rs[8], rq[8], mr[2];
    int s = blockIdx.x, t = threadIdx.x;
    const float* xr = g_q + (size_t)s*FD;
    float x0 = xr[t], x1 = xr[t+256];
    float su = x0+x1, sq = x0*x0 + x1*x1;
    #pragma unroll
    for (int o = 16; o; o >>= 1){ su += __shfl_xor_sync(~0u,su,o); sq += __shfl_xor_sync(~0u,sq,o); }
    if ((t&31)==0){ rs[t>>5]=su; rq[t>>5]=sq; }
    __syncthreads();
    if (t == 0){
        float S=0.f,Q=0.f;
        #pragma unroll
        for (int i=0;i<8;i++){ S+=rs[i]; Q+=rq[i]; }
        float m = S*(1.f/512.f);
        mr[0]=m; mr[1]=rsqrtf(Q*(1.f/512.f)-m*m+1e-5f);
    }
    __syncthreads();
    float m = mr[0], r = mr[1];
    size_t o0 = (size_t)s*FD+t, o1 = o0+256;
    g_qin[o0] = (x0-m)*r*g[t]+b[t] + g_seg_pos[o0];
    g_qin[o1] = (x1-m)*r*g[t+256]+b[t+256] + g_seg_pos[o1];
}

// fused K/V projection (z=0: K -> transposed g_KpT; z=1: V -> g_Vp). M=N=K=512.
__global__ void __launch_bounds__(256) k_gemmKV(const float* __restrict__ A0, const float* __restrict__ A1,
    const float* __restrict__ B0, const float* __restrict__ B1,
    const float* __restrict__ bi0, const float* __restrict__ bi1)
{
    int z = blockIdx.z;
    const float* A = z ? A1 : A0;
    const float* B = z ? B1 : B0;
    const float* bias = z ? bi1 : bi0;
    __shared__ float As[16][68], Bs[16][68];
    int t = threadIdx.x;
    int bm = blockIdx.x*64, bn = blockIdx.y*64;
    int ar = t>>2, ac = (t&3)*4, ty = t>>4, tx = t&15;
    float acc[4][4] = {};
    for (int kk = 0; kk < 512; kk += 16){
        float4 av = *(const float4*)(A + (size_t)(bm+ar)*FD + kk + ac);
        float bv[4];
        #pragma unroll
        for (int j = 0; j < 4; j++){
            int i = t + j*256;
            bv[j] = B[(size_t)(kk+(i>>6))*FD + bn + (i&63)];
        }
        __syncthreads();
        As[ac][ar]=av.x; As[ac+1][ar]=av.y; As[ac+2][ar]=av.z; As[ac+3][ar]=av.w;
        #pragma unroll
        for (int j = 0; j < 4; j++){ int i = t + j*256; Bs[i>>6][i&63] = bv[j]; }
        __syncthreads();
        #pragma unroll
        for (int k = 0; k < 16; k++){
            float4 a4 = *(float4*)&As[k][ty*4];
            float4 b4 = *(float4*)&Bs[k][tx*4];
            #pragma unroll
            for (int i = 0; i < 4; i++)
                #pragma unroll
                for (int j = 0; j < 4; j++)
                    acc[i][j] = fmaf(D4(a4,i), D4(b4,j), acc[i][j]);
        }
    }
    float4 bi = *(const float4*)(bias + bn + tx*4);
    #pragma unroll
    for (int i = 0; i < 4; i++){
        int r = bm + ty*4 + i;
        float o[4] = {acc[i][0]+bi.x, acc[i][1]+bi.y, acc[i][2]+bi.z, acc[i][3]+bi.w};
        if (z){
            *(float4*)(g_Vp + (size_t)r*FD + bn + tx*4) = make_float4(o[0],o[1],o[2],o[3]);
        } else {
            #pragma unroll
            for (int j = 0; j < 4; j++){
                int cc = bn + tx*4 + j;   // column = h*128 + k
                g_KpT[(cc>>7)*65536 + (cc&127)*512 + r] = o[j];
            }
        }
    }
}

// big GEMM: 128x128 tile, 8x8 microtile, double-buffered; blockIdx.z strides
__global__ void __launch_bounds__(256) k_gemm128(const float* __restrict__ A, int lda, size_t sA,
    const float* __restrict__ B, int ldb, size_t sB, const float* __restrict__ bias,
    float* __restrict__ C, int ldc, size_t sC, const float* __restrict__ R, int M, int Kd)
{
    A += (size_t)blockIdx.z*sA; B += (size_t)blockIdx.z*sB; C += (size_t)blockIdx.z*sC;
    __shared__ float As[2][8][128];
    __shared__ float Bs[2][8][128];
    int t = threadIdx.x;
    int bm = blockIdx.x*128, bn = blockIdx.y*128;
    int ty = t>>4, tx = t&15;
    int arow = t>>1, acol = (t&1)*4;
    int brow = t>>5, bcol = (t&31)*4;
    bool aval = (bm + arow) < M;
    const float* Ap = A + (size_t)(bm+arow)*lda + acol;
    const float* Bp = B + (size_t)brow*ldb + bn + bcol;
    float acc[8][8] = {};
    float4 pa = aval ? *(const float4*)Ap : make_float4(0.f,0.f,0.f,0.f);
    float4 pb = *(const float4*)Bp;
    As[0][acol+0][arow]=pa.x; As[0][acol+1][arow]=pa.y; As[0][acol+2][arow]=pa.z; As[0][acol+3][arow]=pa.w;
    *(float4*)&Bs[0][brow][bcol] = pb;
    __syncthreads();
    int buf = 0;
    for (int kk = 8; kk <= Kd; kk += 8){
        bool more = kk < Kd;
        if (more){
            pa = aval ? *(const float4*)(Ap + kk) : make_float4(0.f,0.f,0.f,0.f);
            pb = *(const float4*)(Bp + (size_t)kk*ldb);
        }
        #pragma unroll
        for (int k = 0; k < 8; k++){
            float4 a0 = *(float4*)&As[buf][k][ty*8];
            float4 a1 = *(float4*)&As[buf][k][ty*8+4];
            float4 b0 = *(float4*)&Bs[buf][k][tx*8];
            float4 b1 = *(float4*)&Bs[buf][k][tx*8+4];
            float av[8] = {a0.x,a0.y,a0.z,a0.w,a1.x,a1.y,a1.z,a1.w};
            float bv[8] = {b0.x,b0.y,b0.z,b0.w,b1.x,b1.y,b1.z,b1.w};
            #pragma unroll
            for (int i = 0; i < 8; i++)
                #pragma unroll
                for (int j = 0; j < 8; j++)
                    acc[i][j] = fmaf(av[i], bv[j], acc[i][j]);
        }
        if (more){
            As[buf^1][acol+0][arow]=pa.x; As[buf^1][acol+1][arow]=pa.y;
            As[buf^1][acol+2][arow]=pa.z; As[buf^1][acol+3][arow]=pa.w;
            *(float4*)&Bs[buf^1][brow][bcol] = pb;
        }
        __syncthreads();
        buf ^= 1;
    }
    #pragma unroll
    for (int i = 0; i < 8; i++){
        int r = bm + ty*8 + i;
        if (r < M){
            #pragma unroll
            for (int jj = 0; jj < 2; jj++){
                int c = bn + tx*8 + jj*4;
                float4 o = make_float4(acc[i][jj*4],acc[i][jj*4+1],acc[i][jj*4+2],acc[i][jj*4+3]);
                if (bias){
                    float4 bi = *(const float4*)(bias + c);
                    o.x+=bi.x; o.y+=bi.y; o.z+=bi.z; o.w+=bi.w;
                }
                if (R){
                    float4 r4 = *(const float4*)(R + (size_t)r*ldc + c);
                    o.x+=r4.x; o.y+=r4.y; o.z+=r4.z; o.w+=r4.w;
                }
                *(float4*)(C + (size_t)r*ldc + c) = o;
            }
        }
    }
}

__global__ void k_softmax(){
    int w = threadIdx.x>>5, lane = threadIdx.x&31;
    size_t row = (size_t)blockIdx.x*8 + w;
    float* p = g_att + row*512;
    float v[16], mx = -3.4e38f;
    #pragma unroll
    for (int i=0;i<16;i++){ v[i] = p[lane+32*i]*ATT_SCALE; mx = fmaxf(mx, v[i]); }
    #pragma unroll
    for (int o=16;o;o>>=1) mx = fmaxf(mx, __shfl_xor_sync(~0u,mx,o));
    float s = 0.f;
    #pragma unroll
    for (int i=0;i<16;i++){ v[i] = __expf(v[i]-mx); s += v[i]; }
    #pragma unroll
    for (int o=16;o;o>>=1) s += __shfl_xor_sync(~0u,s,o);
    float inv = 1.f/s;
    #pragma unroll
    for (int i=0;i<16;i++) p[lane+32*i] = v[i]*inv;
}

__global__ void __launch_bounds__(256) k_final(const float* __restrict__ pf, const int* __restrict__ seg,
    const float* __restrict__ c1g, const float* __restrict__ c1b, const float* __restrict__ c1w,
    const float* __restrict__ c1bias, const float* __restrict__ cw, const float* __restrict__ cb,
    float* __restrict__ out)
{
    __shared__ float swT[20][512];
    __shared__ float sg[512], sb[512], sw1[512], scb[20], sc1b;
    int t = threadIdx.x;
    for (int i = t; i < 512*20; i += 256) swT[i%20][i/20] = cw[i];
    for (int i = t; i < 512; i += 256){ sg[i]=c1g[i]; sb[i]=c1b[i]; sw1[i]=c1w[i]; }
    if (t < 20) scb[t] = cb[t];
    if (t == 32) sc1b = c1bias[0];
    __syncthreads();
    int w = t>>5, lane = t&31;
    for (int p = blockIdx.x*8 + w; p < NP; p += gridDim.x*8){
        int s = seg[p];
        const float* fr = g_q + (size_t)s*512;
        const float* pr = pf + (size_t)p*512;
        float f[16], x[16], a[16], su = 0.f, sq = 0.f;
        #pragma unroll
        for (int i=0;i<16;i++){
            int e = lane + 32*i;
            f[i] = fr[e]; x[i] = pr[e];
            a[i] = fabsf(f[i]-x[i]);
            su += a[i]; sq += a[i]*a[i];
        }
        #pragma unroll
        for (int o=16;o;o>>=1){ su += __shfl_xor_sync(~0u,su,o); sq += __shfl_xor_sync(~0u,sq,o); }
        float m = su*(1.f/512.f);
        float rst = rsqrtf(sq*(1.f/512.f) - m*m + 1e-5f);
        float dt = 0.f;
        #pragma unroll
        for (int i=0;i<16;i++){ int e = lane+32*i; dt += ((a[i]-m)*rst*sg[e]+sb[e])*sw1[e]; }
        #pragma unroll
        for (int o=16;o;o>>=1) dt += __shfl_xor_sync(~0u,dt,o);
        float wg = 1.f/(1.f+__expf(-(dt+sc1b)));
        float bl[16];
        #pragma unroll
        for (int i=0;i<16;i++) bl[i] = x[i] + wg*(f[i]-x[i]);
        float* op = out + (size_t)p*20;
        for (int o = 0; o < 20; o++){
            float acc = 0.f;
            #pragma unroll
            for (int i=0;i<16;i++) acc += bl[i]*swT[o][lane+32*i];
            #pragma unroll
            for (int off=16;off;off>>=1) acc += __shfl_xor_sync(~0u,acc,off);
            if (lane == 0) op[o] = acc + scb[o];
        }
    }
}

extern "C" void kernel_launch(void* const* d_in, const int* in_sizes, int n_in,
                              void* d_out, int out_size) {
    const float* pf  = (const float*)d_in[0];
    const float* co  = (const float*)d_in[1];
    const float* fB  = (const float*)d_in[2];
    const float* lng = (const float*)d_in[3];
    const float* lnb = (const float*)d_in[4];
    const float* Wq  = (const float*)d_in[5];
    const float* Wk  = (const float*)d_in[6];
    const float* Wv  = (const float*)d_in[7];
    const float* Wo  = (const float*)d_in[8];
    const float* bq  = (const float*)d_in[9];
    const float* bk  = (const float*)d_in[10];
    const float* bv  = (const float*)d_in[11];
    const float* bo  = (const float*)d_in[12];
    const float* c1g = (const float*)d_in[13];
    const float* c1b = (const float*)d_in[14];
    const float* c1w = (const float*)d_in[15];
    const float* c1bias = (const float*)d_in[16];
    const float* cw  = (const float*)d_in[17];
    const float* cb  = (const float*)d_in[18];
    const int*   seg = (const int*)d_in[19];
    float* out = (float*)d_out;

    static int cfg = 0;
    if (!cfg){ cudaFuncSetAttribute(k_fps, cudaFuncAttributeMaxDynamicSharedMemorySize, FPS_SMEM); cfg = 1; }

    float *gqin, *gQp, *gkf, *gkin, *gatt, *go, *gq;
    cudaGetSymbolAddress((void**)&gqin, g_qin);
    cudaGetSymbolAddress((void**)&gQp,  g_Qp);
    cudaGetSymbolAddress((void**)&gkf,  g_keyfeat);
    cudaGetSymbolAddress((void**)&gkin, g_kin);
    cudaGetSymbolAddress((void**)&gatt, g_att);
    cudaGetSymbolAddress((void**)&go,   g_o);
    cudaGetSymbolAddress((void**)&gq,   g_q);
    float *gKpT, *gVp;
    cudaGetSymbolAddress((void**)&gKpT, g_KpT);
    cudaGetSymbolAddress((void**)&gVp,  g_Vp);

    k_init<<<1,256>>>();
    k_hist<<<HB,256>>>(co, seg);
    k_scan<<<1,1024>>>();
    k_place<<<HB,256>>>(seg);
    k_segreduce<<<SD,256>>>(pf, co, fB);
    k_fps<<<FPS_G,512,FPS_SMEM>>>();
    k_gather<<<KSEL,256>>>();

    dim3 gBig(40,4,1), gLog(40,4,4), gAV(40,1,4), gKV(8,8,2);
    size_t sAtt = (size_t)SD*512;
    for (int L = 0; L < 2; L++){
        const float* wq = Wq + (size_t)L*FD*FD; const float* wk = Wk + (size_t)L*FD*FD;
        const float* wv = Wv + (size_t)L*FD*FD; const float* wo = Wo + (size_t)L*FD*FD;
        k_ln<<<SD,256>>>(lng + L*FD, lnb + L*FD);
        k_gemm128<<<gBig,256>>>(gqin,512,0, wq,512,0, bq+L*FD, gQp,512,0, 0, SD, 512);
        k_gemmKV<<<gKV,256>>>(gkin, gkf, wk, wv, bk+L*FD, bv+L*FD);
        k_gemm128<<<gLog,256>>>(gQp,512,128, gKpT,512,65536, 0, gatt,512,sAtt, 0, SD, 128);
        k_softmax<<<SD*4/8,256>>>();
        k_gemm128<<<gAV,256>>>(gatt,512,sAtt, gVp,512,128, 0, go,512,128, 0, SD, 512);
        k_gemm128<<<gBig,256>>>(go,512,0, wo,512,0, bo+L*FD, gq,512,0, gq, SD, 512);
    }
    k_final<<<600,256>>>(pf, seg, c1g, c1b, c1w, c1bias, cw, cb, out);
}

// round 16
// speedup vs baseline: 1.2528x; 1.0452x over previous
#include <cuda_runtime.h>
#include <math.h>

#define NP 150000
#define FD 512
#define SD 5000
#define KSEL 512
#define HB 150
#define CHUNK 1000
#define FPS_G 148
#define FPS_ROWS 34
#define ATT_SCALE 0.08838834764831845f
#define FPS_SMEM ((FPS_ROWS*FD+FD+FPS_ROWS)*4 + 16*8)
#define D4(v,j) ((j)==0?(v).x:((j)==1?(v).y:((j)==2?(v).z:(v).w)))

__device__ float g_seg_feat[SD*FD], g_seg_pos[SD*FD], g_q[SD*FD], g_qin[SD*FD];
__device__ float g_Qp[SD*FD], g_o[SD*FD];
__device__ float g_KpT[KSEL*FD], g_Vp[KSEL*FD], g_keyfeat[KSEL*FD], g_kin[KSEL*FD];
__device__ float g_att[4*SD*KSEL];
__device__ int g_sorted[NP], g_hist[HB*SD], g_segstart[SD+1], g_minmax[6], g_fps_idx[KSEL];
__device__ unsigned long long g_winner[KSEL];
__device__ unsigned g_barc;

__device__ __forceinline__ unsigned ld_acq_u32(const unsigned* p){
    unsigned v;
    asm volatile("ld.acquire.gpu.u32 %0, [%1];" : "=r"(v) : "l"(p) : "memory");
    return v;
}
__device__ __forceinline__ unsigned long long ld_acq_u64(const unsigned long long* p){
    unsigned long long v;
    asm volatile("ld.acquire.gpu.u64 %0, [%1];" : "=l"(v) : "l"(p) : "memory");
    return v;
}

// sin(2*pi*u), cos(2*pi*u) entirely in the FMA pipe (no MUFU).
__device__ __forceinline__ void sincos2pi(float u, float& s, float& c){
    float t = 4.0f*u;
    float q = rintf(t);
    float r = (t - q)*1.5707963267948966f;   // [-pi/4, pi/4]
    int qi = (int)q;
    float r2 = r*r, r4 = r2*r2;
    float ps = fmaf(-1.9515296e-4f, r2, 8.3321608e-3f);
    ps = fmaf(ps, r2, -1.6666654e-1f);
    ps = fmaf(ps*r2, r, r);
    float pc = fmaf(2.4433157e-5f, r2, -1.3887316e-3f);
    pc = fmaf(pc, r2, 4.1666645e-2f);
    pc = fmaf(pc, r4, fmaf(-0.5f, r2, 1.0f));
    bool sw = qi & 1;
    float ss = sw ? pc : ps;
    float cc = sw ? ps : pc;
    if (qi & 2) ss = -ss;
    if ((qi+1) & 2) cc = -cc;
    s = ss; c = cc;
}

__global__ void k_init(){
    int t = threadIdx.x;
    if (t < 3) g_minmax[t] = 0x7F7FFFFF;
    else if (t < 6) g_minmax[t] = 0;
    if (t == 0){ g_barc = 0u; g_fps_idx[0] = 0; }
    for (int i = t; i < KSEL; i += 256) g_winner[i] = 0ULL;
}

__global__ void k_hist(const float* __restrict__ coords, const int* __restrict__ seg){
    __shared__ int sh[SD];
    int t = threadIdx.x, b = blockIdx.x;
    for (int i = t; i < SD; i += 256) sh[i] = 0;
    __syncthreads();
    int start = b*CHUNK;
    float mn0=3.4e38f,mn1=3.4e38f,mn2=3.4e38f,mx0=-3.4e38f,mx1=-3.4e38f,mx2=-3.4e38f;
    for (int p = start + t; p < start + CHUNK; p += 256){
        atomicAdd(&sh[seg[p]], 1);
        float c0=coords[p*3], c1=coords[p*3+1], c2=coords[p*3+2];
        mn0=fminf(mn0,c0); mn1=fminf(mn1,c1); mn2=fminf(mn2,c2);
        mx0=fmaxf(mx0,c0); mx1=fmaxf(mx1,c1); mx2=fmaxf(mx2,c2);
    }
    __syncthreads();
    for (int s = t; s < SD; s += 256) g_hist[b*SD + s] = sh[s];
    #pragma unroll
    for (int o = 16; o; o >>= 1){
        mn0=fminf(mn0,__shfl_xor_sync(~0u,mn0,o)); mn1=fminf(mn1,__shfl_xor_sync(~0u,mn1,o));
        mn2=fminf(mn2,__shfl_xor_sync(~0u,mn2,o)); mx0=fmaxf(mx0,__shfl_xor_sync(~0u,mx0,o));
        mx1=fmaxf(mx1,__shfl_xor_sync(~0u,mx1,o)); mx2=fmaxf(mx2,__shfl_xor_sync(~0u,mx2,o));
    }
    if ((t & 31) == 0){
        atomicMin(&g_minmax[0], __float_as_int(mn0)); atomicMin(&g_minmax[1], __float_as_int(mn1));
        atomicMin(&g_minmax[2], __float_as_int(mn2)); atomicMax(&g_minmax[3], __float_as_int(mx0));
        atomicMax(&g_minmax[4], __float_as_int(mx1)); atomicMax(&g_minmax[5], __float_as_int(mx2));
    }
}

// scan phase 1: per-segment running sum across blocks (parallel over segments)
__global__ void k_scan1(){
    int s = blockIdx.x*256 + threadIdx.x;
    if (s >= SD) return;
    int run = 0;
    for (int b = 0; b < HB; b++){
        int v = g_hist[b*SD + s];
        g_hist[b*SD + s] = run;
        run += v;
    }
    g_segstart[s] = run;   // segment total for now
}

// scan phase 2: exclusive prefix over the 5000 segment totals (single CTA)
__global__ void k_scan2(){
    __shared__ int gsum[1024];
    int t = threadIdx.x;
    int base = t*5, loc[5], tot[5], sum = 0;
    #pragma unroll
    for (int i = 0; i < 5; i++){
        loc[i] = sum;
        tot[i] = (base+i < SD) ? g_segstart[base+i] : 0;
        sum += tot[i];
    }
    gsum[t] = sum;
    __syncthreads();
    for (int off = 1; off < 1024; off <<= 1){
        int add = (t >= off) ? gsum[t-off] : 0;
        __syncthreads(); gsum[t] += add; __syncthreads();
    }
    int excl = (t > 0) ? gsum[t-1] : 0;
    #pragma unroll
    for (int i = 0; i < 5; i++) if (base+i < SD) g_segstart[base+i] = excl + loc[i];
    if (t == 1023) g_segstart[SD] = gsum[1023];
}

// scan phase 3: add segment bases to per-block offsets (parallel, coalesced)
__global__ void k_scan3(){
    int s = blockIdx.x*256 + threadIdx.x;
    if (s >= SD) return;
    int o = g_segstart[s];
    for (int b = 0; b < HB; b++) g_hist[b*SD + s] += o;
}

__global__ void k_place(const int* __restrict__ seg){
    __shared__ int cur[SD];
    __shared__ int psg[CHUNK];
    int t = threadIdx.x, b = blockIdx.x;
    for (int s = t; s < SD; s += 256) cur[s] = g_hist[b*SD + s];
    for (int i = t; i < CHUNK; i += 256) psg[i] = seg[b*CHUNK + i];
    __syncthreads();
    if (t < 32){
        for (int bs = 0; bs < CHUNK; bs += 32){
            int i = bs + t;
            bool v = i < CHUNK;
            int s = v ? psg[i] : -1 - t;
            unsigned peers = __match_any_sync(0xFFFFFFFFu, s);
            int leader = __ffs(peers) - 1;
            int rank = __popc(peers & ((1u << t) - 1u));
            int pos = 0;
            if (t == leader && v){ pos = cur[s]; cur[s] = pos + __popc(peers); }
            pos = __shfl_sync(0xFFFFFFFFu, pos, leader);
            if (v) g_sorted[pos + rank] = b*CHUNK + i;
        }
    }
}

__global__ void k_segreduce(const float* __restrict__ pf, const float* __restrict__ coords,
                            const float* __restrict__ fB){
    __shared__ float sB0[256], sB1[256], sB2[256];
    int t = threadIdx.x, s = blockIdx.x;
    sB0[t] = fB[t]; sB1[t] = fB[256+t]; sB2[t] = fB[512+t];
    float mn0 = __int_as_float(g_minmax[0]), mn1 = __int_as_float(g_minmax[1]), mn2 = __int_as_float(g_minmax[2]);
    float i0 = 1.f/(__int_as_float(g_minmax[3])-mn0+1e-6f);
    float i1 = 1.f/(__int_as_float(g_minmax[4])-mn1+1e-6f);
    float i2 = 1.f/(__int_as_float(g_minmax[5])-mn2+1e-6f);
    __syncthreads();
    int st = g_segstart[s], en = g_segstart[s+1];
    float aS=0.f, aC=0.f, a0=0.f, a1=0.f;
    int i = st;
    for (; i + 1 < en; i += 2){
        int pA = g_sorted[i], pB = g_sorted[i+1];
        float cA0=(coords[pA*3]-mn0)*i0, cA1=(coords[pA*3+1]-mn1)*i1, cA2=(coords[pA*3+2]-mn2)*i2;
        float cB0=(coords[pB*3]-mn0)*i0, cB1=(coords[pB*3+1]-mn1)*i1, cB2=(coords[pB*3+2]-mn2)*i2;
        const float* rA = pf + (size_t)pA*FD;
        const float* rB = pf + (size_t)pB*FD;
        float fA0 = rA[t], fA1 = rA[t+256];
        float fB0_ = rB[t], fB1_ = rB[t+256];
        float uA = cA0*sB0[t] + cA1*sB1[t] + cA2*sB2[t];
        float uB = cB0*sB0[t] + cB1*sB1[t] + cB2*sB2[t];
        float svA, cvA, svB, cvB;
        sincos2pi(uA, svA, cvA);
        sincos2pi(uB, svB, cvB);
        // sequential accumulation in original point order (bitwise-identical)
        aS += svA; aC += cvA; a0 += fA0; a1 += fA1;
        aS += svB; aC += cvB; a0 += fB0_; a1 += fB1_;
    }
    for (; i < en; i++){
        int p = g_sorted[i];
        float c0=(coords[p*3]-mn0)*i0, c1=(coords[p*3+1]-mn1)*i1, c2=(coords[p*3+2]-mn2)*i2;
        float u = c0*sB0[t] + c1*sB1[t] + c2*sB2[t];
        float sv, cv; sincos2pi(u, sv, cv);
        aS += sv; aC += cv;
        const float* r = pf + (size_t)p*FD;
        a0 += r[t]; a1 += r[t+256];
    }
    float ic = 1.f/fmaxf((float)(en-st), 1.f);
    int o0 = s*FD + t, o1 = o0 + 256;
    g_seg_pos[o0] = aS*ic; g_seg_pos[o1] = aC*ic;
    float f0 = a0*ic, f1 = a1*ic;
    g_seg_feat[o0]=f0; g_seg_feat[o1]=f1; g_q[o0]=f0; g_q[o1]=f1;
}

// FPS: R14 kernel verbatim (proven): 148x512x34, fused in-loop argmax,
// atomicMax + counter + acquire spin.
__global__ void __launch_bounds__(512) k_fps(){
    extern __shared__ float sm[];
    float* srows = sm;                    // FPS_ROWS*FD
    float* scur  = sm + FPS_ROWS*FD;      // FD
    float* sdmin = scur + FD;             // FPS_ROWS
    unsigned long long* sbest = (unsigned long long*)(sdmin + FPS_ROWS);  // 16
    __shared__ int s_cur;
    int t = threadIdx.x, b = blockIdx.x;
    int r0 = b*FPS_ROWS;
    int nrows = SD - r0; if (nrows > FPS_ROWS) nrows = FPS_ROWS; if (nrows < 0) nrows = 0;
    for (int i = t; i < nrows*FD; i += 512) srows[i] = g_seg_pos[r0*FD + i];
    for (int r = t; r < nrows; r += 512) sdmin[r] = 1e10f;
    if (t == 0) s_cur = 0;
    __syncthreads();
    int w = t>>5, lane = t&31;
    for (int step = 1; step < KSEL; step++){
        int cur = s_cur;
        for (int e = t; e < FD; e += 512) scur[e] = g_seg_pos[cur*FD + e];
        __syncthreads();
        float c[16];
        #pragma unroll
        for (int i = 0; i < 16; i++) c[i] = scur[lane + 32*i];
        unsigned long long wbest = 0ULL;
        for (int r = w; r < nrows; r += 16){
            const float* rp = srows + r*FD + lane;
            float acc = 0.f;
            #pragma unroll
            for (int i = 0; i < 16; i++){ float d = rp[32*i] - c[i]; acc = fmaf(d,d,acc); }
            #pragma unroll
            for (int o = 16; o; o >>= 1) acc += __shfl_xor_sync(~0u, acc, o);
            if (lane == 0){
                float nv = fminf(sdmin[r], acc);
                sdmin[r] = nv;
                unsigned long long pk = ((unsigned long long)__float_as_uint(nv)<<32)
                                      | (unsigned long long)(0xFFFFFFFFu - (unsigned)(r0+r));
                if (pk > wbest) wbest = pk;
            }
        }
        if (lane == 0) sbest[w] = wbest;
        __syncthreads();
        if (w == 0){
            unsigned long long best = (lane < 16) ? sbest[lane] : 0ULL;
            #pragma unroll
            for (int o = 16; o; o >>= 1){
                unsigned long long v = __shfl_xor_sync(~0u, best, o);
                if (v > best) best = v;
            }
            if (lane == 0){
                atomicMax(&g_winner[step], best);
                __threadfence();
                atomicAdd(&g_barc, 1u);
                unsigned target = (unsigned)step * FPS_G;
                while (ld_acq_u32(&g_barc) < target) { }
                unsigned long long wv = ld_acq_u64(&g_winner[step]);
                int sel = (int)(0xFFFFFFFFu - (unsigned)(wv & 0xFFFFFFFFull));
                s_cur = sel;
                if (b == 0) g_fps_idx[step] = sel;
            }
        }
        __syncthreads();
    }
}

__global__ void k_gather(){
    int k = blockIdx.x, t = threadIdx.x;
    int s = g_fps_idx[k];
    float f0 = g_seg_feat[s*FD+t], f1 = g_seg_feat[s*FD+t+256];
    float p0 = g_seg_pos[s*FD+t],  p1 = g_seg_pos[s*FD+t+256];
    g_keyfeat[k*FD+t] = f0;     g_keyfeat[k*FD+t+256] = f1;
    g_kin[k*FD+t] = f0+p0;      g_kin[k*FD+t+256] = f1+p1;
}

__global__ void k_ln(const float* __restrict__ g, const float* __restrict__ b){
    __shared__ float rs[8], rq[8], mr[2];
    int s = blockIdx.x, t = threadIdx.x;
    const float* xr = g_q + (size_t)s*FD;
    float x0 = xr[t], x1 = xr[t+256];
    float su = x0+x1, sq = x0*x0 + x1*x1;
    #pragma unroll
    for (int o = 16; o; o >>= 1){ su += __shfl_xor_sync(~0u,su,o); sq += __shfl_xor_sync(~0u,sq,o); }
    if ((t&31)==0){ rs[t>>5]=su; rq[t>>5]=sq; }
    __syncthreads();
    if (t == 0){
        float S=0.f,Q=0.f;
        #pragma unroll
        for (int i=0;i<8;i++){ S+=rs[i]; Q+=rq[i]; }
        float m = S*(1.f/512.f);
        mr[0]=m; mr[1]=rsqrtf(Q*(1.f/512.f)-m*m+1e-5f);
    }
    __syncthreads();
    float m = mr[0], r = mr[1];
    size_t o0 = (size_t)s*FD+t, o1 = o0+256;
    g_qin[o0] = (x0-m)*r*g[t]+b[t] + g_seg_pos[o0];
    g_qin[o1] = (x1-m)*r*g[t+256]+b[t+256] + g_seg_pos[o1];
}

// fused K/V projection (z=0: K -> transposed g_KpT; z=1: V -> g_Vp). M=N=K=512.
__global__ void __launch_bounds__(256) k_gemmKV(const float* __restrict__ A0, const float* __restrict__ A1,
    const float* __restrict__ B0, const float* __restrict__ B1,
    const float* __restrict__ bi0, const float* __restrict__ bi1)
{
    int z = blockIdx.z;
    const float* A = z ? A1 : A0;
    const float* B = z ? B1 : B0;
    const float* bias = z ? bi1 : bi0;
    __shared__ float As[16][68], Bs[16][68];
    int t = threadIdx.x;
    int bm = blockIdx.x*64, bn = blockIdx.y*64;
    int ar = t>>2, ac = (t&3)*4, ty = t>>4, tx = t&15;
    float acc[4][4] = {};
    for (int kk = 0; kk < 512; kk += 16){
        float4 av = *(const float4*)(A + (size_t)(bm+ar)*FD + kk + ac);
        float bv[4];
        #pragma unroll
        for (int j = 0; j < 4; j++){
            int i = t + j*256;
            bv[j] = B[(size_t)(kk+(i>>6))*FD + bn + (i&63)];
        }
        __syncthreads();
        As[ac][ar]=av.x; As[ac+1][ar]=av.y; As[ac+2][ar]=av.z; As[ac+3][ar]=av.w;
        #pragma unroll
        for (int j = 0; j < 4; j++){ int i = t + j*256; Bs[i>>6][i&63] = bv[j]; }
        __syncthreads();
        #pragma unroll
        for (int k = 0; k < 16; k++){
            float4 a4 = *(float4*)&As[k][ty*4];
            float4 b4 = *(float4*)&Bs[k][tx*4];
            #pragma unroll
            for (int i = 0; i < 4; i++)
                #pragma unroll
                for (int j = 0; j < 4; j++)
                    acc[i][j] = fmaf(D4(a4,i), D4(b4,j), acc[i][j]);
        }
    }
    float4 bi = *(const float4*)(bias + bn + tx*4);
    #pragma unroll
    for (int i = 0; i < 4; i++){
        int r = bm + ty*4 + i;
        float o[4] = {acc[i][0]+bi.x, acc[i][1]+bi.y, acc[i][2]+bi.z, acc[i][3]+bi.w};
        if (z){
            *(float4*)(g_Vp + (size_t)r*FD + bn + tx*4) = make_float4(o[0],o[1],o[2],o[3]);
        } else {
            #pragma unroll
            for (int j = 0; j < 4; j++){
                int cc = bn + tx*4 + j;   // column = h*128 + k
                g_KpT[(cc>>7)*65536 + (cc&127)*512 + r] = o[j];
            }
        }
    }
}

// big GEMM: 128x128 tile, 8x8 microtile, double-buffered; 2 CTAs/SM
__global__ void __launch_bounds__(256,2) k_gemm128(const float* __restrict__ A, int lda, size_t sA,
    const float* __restrict__ B, int ldb, size_t sB, const float* __restrict__ bias,
    float* __restrict__ C, int ldc, size_t sC, const float* __restrict__ R, int M, int Kd)
{
    A += (size_t)blockIdx.z*sA; B += (size_t)blockIdx.z*sB; C += (size_t)blockIdx.z*sC;
    __shared__ float As[2][8][128];
    __shared__ float Bs[2][8][128];
    int t = threadIdx.x;
    int bm = blockIdx.x*128, bn = blockIdx.y*128;
    int ty = t>>4, tx = t&15;
    int arow = t>>1, acol = (t&1)*4;
    int brow = t>>5, bcol = (t&31)*4;
    bool aval = (bm + arow) < M;
    const float* Ap = A + (size_t)(bm+arow)*lda + acol;
    const float* Bp = B + (size_t)brow*ldb + bn + bcol;
    float acc[8][8] = {};
    float4 pa = aval ? *(const float4*)Ap : make_float4(0.f,0.f,0.f,0.f);
    float4 pb = *(const float4*)Bp;
    As[0][acol+0][arow]=pa.x; As[0][acol+1][arow]=pa.y; As[0][acol+2][arow]=pa.z; As[0][acol+3][arow]=pa.w;
    *(float4*)&Bs[0][brow][bcol] = pb;
    __syncthreads();
    int buf = 0;
    for (int kk = 8; kk <= Kd; kk += 8){
        bool more = kk < Kd;
        if (more){
            pa = aval ? *(const float4*)(Ap + kk) : make_float4(0.f,0.f,0.f,0.f);
            pb = *(const float4*)(Bp + (size_t)kk*ldb);
        }
        #pragma unroll
        for (int k = 0; k < 8; k++){
            float4 a0 = *(float4*)&As[buf][k][ty*8];
            float4 a1 = *(float4*)&As[buf][k][ty*8+4];
            float4 b0 = *(float4*)&Bs[buf][k][tx*8];
            float4 b1 = *(float4*)&Bs[buf][k][tx*8+4];
            float av[8] = {a0.x,a0.y,a0.z,a0.w,a1.x,a1.y,a1.z,a1.w};
            float bv[8] = {b0.x,b0.y,b0.z,b0.w,b1.x,b1.y,b1.z,b1.w};
            #pragma unroll
            for (int i = 0; i < 8; i++)
                #pragma unroll
                for (int j = 0; j < 8; j++)
                    acc[i][j] = fmaf(av[i], bv[j], acc[i][j]);
        }
        if (more){
            As[buf^1][acol+0][arow]=pa.x; As[buf^1][acol+1][arow]=pa.y;
            As[buf^1][acol+2][arow]=pa.z; As[buf^1][acol+3][arow]=pa.w;
            *(float4*)&Bs[buf^1][brow][bcol] = pb;
        }
        __syncthreads();
        buf ^= 1;
    }
    #pragma unroll
    for (int i = 0; i < 8; i++){
        int r = bm + ty*8 + i;
        if (r < M){
            #pragma unroll
            for (int jj = 0; jj < 2; jj++){
                int c = bn + tx*8 + jj*4;
                float4 o = make_float4(acc[i][jj*4],acc[i][jj*4+1],acc[i][jj*4+2],acc[i][jj*4+3]);
                if (bias){
                    float4 bi = *(const float4*)(bias + c);
                    o.x+=bi.x; o.y+=bi.y; o.z+=bi.z; o.w+=bi.w;
                }
                if (R){
                    float4 r4 = *(const float4*)(R + (size_t)r*ldc + c);
                    o.x+=r4.x; o.y+=r4.y; o.z+=r4.z; o.w+=r4.w;
                }
                *(float4*)(C + (size_t)r*ldc + c) = o;
            }
        }
    }
}

__global__ void k_softmax(){
    int w = threadIdx.x>>5, lane = threadIdx.x&31;
    size_t row = (size_t)blockIdx.x*8 + w;
    float* p = g_att + row*512;
    float v[16], mx = -3.4e38f;
    #pragma unroll
    for (int i=0;i<16;i++){ v[i] = p[lane+32*i]*ATT_SCALE; mx = fmaxf(mx, v[i]); }
    #pragma unroll
    for (int o=16;o;o>>=1) mx = fmaxf(mx, __shfl_xor_sync(~0u,mx,o));
    float s = 0.f;
    #pragma unroll
    for (int i=0;i<16;i++){ v[i] = __expf(v[i]-mx); s += v[i]; }
    #pragma unroll
    for (int o=16;o;o>>=1) s += __shfl_xor_sync(~0u,s,o);
    float inv = 1.f/s;
    #pragma unroll
    for (int i=0;i<16;i++) p[lane+32*i] = v[i]*inv;
}

__global__ void __launch_bounds__(256) k_final(const float* __restrict__ pf, const int* __restrict__ seg,
    const float* __restrict__ c1g, const float* __restrict__ c1b, const float* __restrict__ c1w,
    const float* __restrict__ c1bias, const float* __restrict__ cw, const float* __restrict__ cb,
    float* __restrict__ out)
{
    __shared__ float swT[20][512];
    __shared__ float sg[512], sb[512], sw1[512], scb[20], sc1b;
    int t = threadIdx.x;
    for (int i = t; i < 512*20; i += 256) swT[i%20][i/20] = cw[i];
    for (int i = t; i < 512; i += 256){ sg[i]=c1g[i]; sb[i]=c1b[i]; sw1[i]=c1w[i]; }
    if (t < 20) scb[t] = cb[t];
    if (t == 32) sc1b = c1bias[0];
    __syncthreads();
    int w = t>>5, lane = t&31;
    for (int p = blockIdx.x*8 + w; p < NP; p += gridDim.x*8){
        int s = seg[p];
        const float* fr = g_q + (size_t)s*512;
        const float* pr = pf + (size_t)p*512;
        float f[16], x[16], a[16], su = 0.f, sq = 0.f;
        #pragma unroll
        for (int i=0;i<16;i++){
            int e = lane + 32*i;
            f[i] = fr[e]; x[i] = pr[e];
            a[i] = fabsf(f[i]-x[i]);
            su += a[i]; sq += a[i]*a[i];
        }
        #pragma unroll
        for (int o=16;o;o>>=1){ su += __shfl_xor_sync(~0u,su,o); sq += __shfl_xor_sync(~0u,sq,o); }
        float m = su*(1.f/512.f);
        float rst = rsqrtf(sq*(1.f/512.f) - m*m + 1e-5f);
        float dt = 0.f;
        #pragma unroll
        for (int i=0;i<16;i++){ int e = lane+32*i; dt += ((a[i]-m)*rst*sg[e]+sb[e])*sw1[e]; }
        #pragma unroll
        for (int o=16;o;o>>=1) dt += __shfl_xor_sync(~0u,dt,o);
        float wg = 1.f/(1.f+__expf(-(dt+sc1b)));
        float bl[16];
        #pragma unroll
        for (int i=0;i<16;i++) bl[i] = x[i] + wg*(f[i]-x[i]);
        float* op = out + (size_t)p*20;
        for (int o = 0; o < 20; o++){
            float acc = 0.f;
            #pragma unroll
            for (int i=0;i<16;i++) acc += bl[i]*swT[o][lane+32*i];
            #pragma unroll
            for (int off=16;off;off>>=1) acc += __shfl_xor_sync(~0u,acc,off);
            if (lane == 0) op[o] = acc + scb[o];
        }
    }
}

extern "C" void kernel_launch(void* const* d_in, const int* in_sizes, int n_in,
                              void* d_out, int out_size) {
    const float* pf  = (const float*)d_in[0];
    const float* co  = (const float*)d_in[1];
    const float* fB  = (const float*)d_in[2];
    const float* lng = (const float*)d_in[3];
    const float* lnb = (const float*)d_in[4];
    const float* Wq  = (const float*)d_in[5];
    const float* Wk  = (const float*)d_in[6];
    const float* Wv  = (const float*)d_in[7];
    const float* Wo  = (const float*)d_in[8];
    const float* bq  = (const float*)d_in[9];
    const float* bk  = (const float*)d_in[10];
    const float* bv  = (const float*)d_in[11];
    const float* bo  = (const float*)d_in[12];
    const float* c1g = (const float*)d_in[13];
    const float* c1b = (const float*)d_in[14];
    const float* c1w = (const float*)d_in[15];
    const float* c1bias = (const float*)d_in[16];
    const float* cw  = (const float*)d_in[17];
    const float* cb  = (const float*)d_in[18];
    const int*   seg = (const int*)d_in[19];
    float* out = (float*)d_out;

    static int cfg = 0;
    if (!cfg){ cudaFuncSetAttribute(k_fps, cudaFuncAttributeMaxDynamicSharedMemorySize, FPS_SMEM); cfg = 1; }

    float *gqin, *gQp, *gkf, *gkin, *gatt, *go, *gq;
    cudaGetSymbolAddress((void**)&gqin, g_qin);
    cudaGetSymbolAddress((void**)&gQp,  g_Qp);
    cudaGetSymbolAddress((void**)&gkf,  g_keyfeat);
    cudaGetSymbolAddress((void**)&gkin, g_kin);
    cudaGetSymbolAddress((void**)&gatt, g_att);
    cudaGetSymbolAddress((void**)&go,   g_o);
    cudaGetSymbolAddress((void**)&gq,   g_q);
    float *gKpT, *gVp;
    cudaGetSymbolAddress((void**)&gKpT, g_KpT);
    cudaGetSymbolAddress((void**)&gVp,  g_Vp);

    k_init<<<1,256>>>();
    k_hist<<<HB,256>>>(co, seg);
    k_scan1<<<20,256>>>();
    k_scan2<<<1,1024>>>();
    k_scan3<<<20,256>>>();
    k_place<<<HB,256>>>(seg);
    k_segreduce<<<SD,256>>>(pf, co, fB);
    k_fps<<<FPS_G,512,FPS_SMEM>>>();
    k_gather<<<KSEL,256>>>();

    dim3 gBig(40,4,1), gLog(40,4,4), gAV(40,1,4), gKV(8,8,2);
    size_t sAtt = (size_t)SD*512;
    for (int L = 0; L < 2; L++){
        const float* wq = Wq + (size_t)L*FD*FD; const float* wk = Wk + (size_t)L*FD*FD;
        const float* wv = Wv + (size_t)L*FD*FD; const float* wo = Wo + (size_t)L*FD*FD;
        k_ln<<<SD,256>>>(lng + L*FD, lnb + L*FD);
        k_gemm128<<<gBig,256>>>(gqin,512,0, wq,512,0, bq+L*FD, gQp,512,0, 0, SD, 512);
        k_gemmKV<<<gKV,256>>>(gkin, gkf, wk, wv, bk+L*FD, bv+L*FD);
        k_gemm128<<<gLog,256>>>(gQp,512,128, gKpT,512,65536, 0, gatt,512,sAtt, 0, SD, 128);
        k_softmax<<<SD*4/8,256>>>();
        k_gemm128<<<gAV,256>>>(gatt,512,sAtt, gVp,512,128, 0, go,512,128, 0, SD, 512);
        k_gemm128<<<gBig,256>>>(go,512,0, wo,512,0, bo+L*FD, gq,512,0, gq, SD, 512);
    }
    k_final<<<600,256>>>(pf, seg, c1g, c1b, c1w, c1bias, cw, cb, out);
}